// round 2
// baseline (speedup 1.0000x reference)
#include <cuda_runtime.h>
#include <cstdint>
#include <math.h>

#define EPSF 1e-5f

static const int N_TOK = 16384;   // B*T = 8*2048
static const int DIM   = 1024;
static const int FF    = 4096;

// ---------------- scratch (device globals; allocation-free) ----------------
__device__ int8_t   g_w1q[(size_t)FF * DIM];      // 4 MB
__device__ int8_t   g_w2q[(size_t)DIM * FF];      // 4 MB
__device__ int8_t   g_a1 [(size_t)N_TOK * DIM];   // 16 MB
__device__ int8_t   g_a2 [(size_t)N_TOK * FF];    // 64 MB
__device__ float    g_h  [(size_t)N_TOK * FF];    // 256 MB
__device__ float    g_dqa1[N_TOK];
__device__ unsigned g_hmax[N_TOK];                // float bits, idempotent max
__device__ unsigned g_wmax[2];                    // float bits

// ---------------- per-tensor absmax ----------------
template<int WI>
__global__ void absmax_k(const float4* __restrict__ x, int n4) {
    float m = 0.f;
    for (int i = blockIdx.x * blockDim.x + threadIdx.x; i < n4; i += gridDim.x * blockDim.x) {
        float4 v = x[i];
        m = fmaxf(m, fmaxf(fmaxf(fabsf(v.x), fabsf(v.y)), fmaxf(fabsf(v.z), fabsf(v.w))));
    }
    #pragma unroll
    for (int o = 16; o; o >>= 1) m = fmaxf(m, __shfl_xor_sync(0xffffffffu, m, o));
    __shared__ float sh[32];
    if ((threadIdx.x & 31) == 0) sh[threadIdx.x >> 5] = m;
    __syncthreads();
    if (threadIdx.x < 32) {
        m = (threadIdx.x < (blockDim.x >> 5)) ? sh[threadIdx.x] : 0.f;
        #pragma unroll
        for (int o = 16; o; o >>= 1) m = fmaxf(m, __shfl_xor_sync(0xffffffffu, m, o));
        if (threadIdx.x == 0) atomicMax(&g_wmax[WI], __float_as_uint(m));
    }
}

// ---------------- weight int8 quantize ----------------
template<int WI>
__global__ void quantw_k(const float4* __restrict__ w, int n4) {
    int i = blockIdx.x * blockDim.x + threadIdx.x;
    if (i >= n4) return;
    float s = 127.f / fmaxf(__uint_as_float(g_wmax[WI]), EPSF);
    float4 v = w[i];
    char4 o;
    o.x = (char)(int)rintf(fminf(fmaxf(v.x * s, -127.f), 127.f));
    o.y = (char)(int)rintf(fminf(fmaxf(v.y * s, -127.f), 127.f));
    o.z = (char)(int)rintf(fminf(fmaxf(v.z * s, -127.f), 127.f));
    o.w = (char)(int)rintf(fminf(fmaxf(v.w * s, -127.f), 127.f));
    ((char4*)(WI == 0 ? g_w1q : g_w2q))[i] = o;
}

// ---------------- fused LayerNorm + per-token act quant ----------------
__global__ void ln_quant_k(const float4* __restrict__ x,
                           const float4* __restrict__ gamma,
                           const float4* __restrict__ beta) {
    const int row = blockIdx.x;
    const int t   = threadIdx.x;           // 256 threads, D/4 = 256 float4
    __shared__ float sh[8];

    float4 v = x[(size_t)row * 256 + t];

    // block sum helper (8 warps)
    float s = v.x + v.y + v.z + v.w;
    #pragma unroll
    for (int o = 16; o; o >>= 1) s += __shfl_xor_sync(0xffffffffu, s, o);
    if ((t & 31) == 0) sh[t >> 5] = s;
    __syncthreads();
    float mu = sh[0];
    #pragma unroll
    for (int i = 1; i < 8; i++) mu += sh[i];
    mu *= (1.f / 1024.f);
    __syncthreads();

    float d0 = v.x - mu, d1 = v.y - mu, d2 = v.z - mu, d3 = v.w - mu;
    float ss = d0*d0 + d1*d1 + d2*d2 + d3*d3;
    #pragma unroll
    for (int o = 16; o; o >>= 1) ss += __shfl_xor_sync(0xffffffffu, ss, o);
    if ((t & 31) == 0) sh[t >> 5] = ss;
    __syncthreads();
    float var = sh[0];
    #pragma unroll
    for (int i = 1; i < 8; i++) var += sh[i];
    var *= (1.f / 1024.f);
    __syncthreads();

    float rstd = rsqrtf(var + EPSF);
    float4 g = gamma[t], b = beta[t];
    float y0 = d0 * rstd * g.x + b.x;
    float y1 = d1 * rstd * g.y + b.y;
    float y2 = d2 * rstd * g.z + b.z;
    float y3 = d3 * rstd * g.w + b.w;

    float am = fmaxf(fmaxf(fabsf(y0), fabsf(y1)), fmaxf(fabsf(y2), fabsf(y3)));
    #pragma unroll
    for (int o = 16; o; o >>= 1) am = fmaxf(am, __shfl_xor_sync(0xffffffffu, am, o));
    if ((t & 31) == 0) sh[t >> 5] = am;
    __syncthreads();
    float amax = sh[0];
    #pragma unroll
    for (int i = 1; i < 8; i++) amax = fmaxf(amax, sh[i]);

    amax = fmaxf(amax, EPSF);
    float sc = 127.f / amax;
    char4 o;
    o.x = (char)(int)rintf(fminf(fmaxf(y0 * sc, -127.f), 127.f));
    o.y = (char)(int)rintf(fminf(fmaxf(y1 * sc, -127.f), 127.f));
    o.z = (char)(int)rintf(fminf(fmaxf(y2 * sc, -127.f), 127.f));
    o.w = (char)(int)rintf(fminf(fmaxf(y3 * sc, -127.f), 127.f));
    ((char4*)g_a1)[(size_t)row * 256 + t] = o;
    if (t == 0) g_dqa1[row] = amax * (1.f / 127.f);
}

// ---------------- int8 GEMM (mma.sync m16n8k32), BM=BN=128, BK=64 ----------------
// EPI==1: C = a1 @ w1q^T ; fuse dequant+bias+swish, write g_h + row absmax
// EPI==2: C = a2 @ w2q^T ; fuse dequant+bias+mask+residual, write out
template<int EPI>
__launch_bounds__(128)
__global__ void gemm_s8_k(const float* __restrict__ bias,
                          const float* __restrict__ xres,
                          const float* __restrict__ mask,
                          float* __restrict__ out) {
    constexpr int K = (EPI == 1) ? DIM : FF;
    const int8_t* __restrict__ A  = (EPI == 1) ? g_a1  : g_a2;
    const int8_t* __restrict__ Bw = (EPI == 1) ? g_w1q : g_w2q;

    __shared__ __align__(16) int8_t sA[2][128][80];
    __shared__ __align__(16) int8_t sB[2][128][80];

    const int tid  = threadIdx.x;
    const int lane = tid & 31;
    const int warp = tid >> 5;
    const int wm   = warp >> 1, wn = warp & 1;
    const int bm   = blockIdx.y * 128;
    const int bn   = blockIdx.x * 128;

    int acc[4][8][4];
    #pragma unroll
    for (int mi = 0; mi < 4; mi++)
        #pragma unroll
        for (int ni = 0; ni < 8; ni++)
            #pragma unroll
            for (int j = 0; j < 4; j++) acc[mi][ni][j] = 0;

    const int ldr = tid >> 2;          // 0..31
    const int ldc = (tid & 3) * 16;    // 0/16/32/48

    auto ld_tile = [&](int buf, int kt) {
        const int8_t* ga = A  + (size_t)(bm + ldr) * K + kt * 64 + ldc;
        const int8_t* gb = Bw + (size_t)(bn + ldr) * K + kt * 64 + ldc;
        #pragma unroll
        for (int i = 0; i < 4; i++) {
            unsigned da = (unsigned)__cvta_generic_to_shared(&sA[buf][ldr + 32 * i][ldc]);
            asm volatile("cp.async.cg.shared.global [%0], [%1], 16;\n" :: "r"(da), "l"(ga + (size_t)32 * i * K));
            unsigned db = (unsigned)__cvta_generic_to_shared(&sB[buf][ldr + 32 * i][ldc]);
            asm volatile("cp.async.cg.shared.global [%0], [%1], 16;\n" :: "r"(db), "l"(gb + (size_t)32 * i * K));
        }
        asm volatile("cp.async.commit_group;\n");
    };

    const int KT = K / 64;
    ld_tile(0, 0);
    int buf = 0;
    for (int kt = 0; kt < KT; ++kt) {
        asm volatile("cp.async.wait_group 0;\n");
        __syncthreads();
        if (kt + 1 < KT) ld_tile(buf ^ 1, kt + 1);
        #pragma unroll
        for (int ks = 0; ks < 2; ++ks) {
            unsigned af[4][4], bf[8][2];
            const int c0 = ks * 32 + (lane & 3) * 4;
            #pragma unroll
            for (int mi = 0; mi < 4; mi++) {
                int r = wm * 64 + mi * 16 + (lane >> 2);
                af[mi][0] = *(const unsigned*)&sA[buf][r][c0];
                af[mi][1] = *(const unsigned*)&sA[buf][r + 8][c0];
                af[mi][2] = *(const unsigned*)&sA[buf][r][c0 + 16];
                af[mi][3] = *(const unsigned*)&sA[buf][r + 8][c0 + 16];
            }
            #pragma unroll
            for (int ni = 0; ni < 8; ni++) {
                int r = wn * 64 + ni * 8 + (lane >> 2);
                bf[ni][0] = *(const unsigned*)&sB[buf][r][c0];
                bf[ni][1] = *(const unsigned*)&sB[buf][r][c0 + 16];
            }
            #pragma unroll
            for (int mi = 0; mi < 4; mi++)
                #pragma unroll
                for (int ni = 0; ni < 8; ni++)
                    asm volatile(
                        "mma.sync.aligned.m16n8k32.row.col.s32.s8.s8.s32 "
                        "{%0,%1,%2,%3}, {%4,%5,%6,%7}, {%8,%9}, {%0,%1,%2,%3};\n"
                        : "+r"(acc[mi][ni][0]), "+r"(acc[mi][ni][1]),
                          "+r"(acc[mi][ni][2]), "+r"(acc[mi][ni][3])
                        : "r"(af[mi][0]), "r"(af[mi][1]), "r"(af[mi][2]), "r"(af[mi][3]),
                          "r"(bf[ni][0]), "r"(bf[ni][1]));
        }
        buf ^= 1;
    }

    const float dqw = fmaxf(__uint_as_float(g_wmax[EPI - 1]), EPSF) * (1.f / 127.f);

    if (EPI == 1) {
        #pragma unroll
        for (int mi = 0; mi < 4; mi++) {
            #pragma unroll
            for (int half = 0; half < 2; ++half) {
                int row = bm + wm * 64 + mi * 16 + (lane >> 2) + half * 8;
                float f = g_dqa1[row] * dqw;
                float rmax = 0.f;
                #pragma unroll
                for (int ni = 0; ni < 8; ni++) {
                    #pragma unroll
                    for (int j = 0; j < 2; j++) {
                        int col = bn + wn * 64 + ni * 8 + (lane & 3) * 2 + j;
                        float v  = (float)acc[mi][ni][half * 2 + j] * f + bias[col];
                        float hv = v / (1.f + expf(-v));   // v * sigmoid(v)
                        g_h[(size_t)row * FF + col] = hv;
                        rmax = fmaxf(rmax, fabsf(hv));
                    }
                }
                rmax = fmaxf(rmax, __shfl_xor_sync(0xffffffffu, rmax, 1));
                rmax = fmaxf(rmax, __shfl_xor_sync(0xffffffffu, rmax, 2));
                if ((lane & 3) == 0) atomicMax(&g_hmax[row], __float_as_uint(rmax));
            }
        }
    } else {
        #pragma unroll
        for (int mi = 0; mi < 4; mi++) {
            #pragma unroll
            for (int half = 0; half < 2; ++half) {
                int row = bm + wm * 64 + mi * 16 + (lane >> 2) + half * 8;
                float f  = fmaxf(__uint_as_float(g_hmax[row]), EPSF) * (1.f / 127.f) * dqw;
                float mk = mask[row];
                #pragma unroll
                for (int ni = 0; ni < 8; ni++) {
                    #pragma unroll
                    for (int j = 0; j < 2; j++) {
                        int col = bn + wn * 64 + ni * 8 + (lane & 3) * 2 + j;
                        float v = (float)acc[mi][ni][half * 2 + j] * f + bias[col];
                        out[(size_t)row * DIM + col] =
                            xres[(size_t)row * DIM + col] + 0.5f * v * mk;
                    }
                }
            }
        }
    }
}

// ---------------- per-row quantize of h -> int8 ----------------
__global__ void quant_h_k() {
    int i = blockIdx.x * blockDim.x + threadIdx.x;   // over N_TOK*FF/4 = 16,777,216
    int row = i >> 10;                                // FF/4 = 1024 float4 per row
    float s = 127.f / fmaxf(__uint_as_float(g_hmax[row]), EPSF);
    float4 v = ((const float4*)g_h)[i];
    char4 o;
    o.x = (char)(int)rintf(fminf(fmaxf(v.x * s, -127.f), 127.f));
    o.y = (char)(int)rintf(fminf(fmaxf(v.y * s, -127.f), 127.f));
    o.z = (char)(int)rintf(fminf(fmaxf(v.z * s, -127.f), 127.f));
    o.w = (char)(int)rintf(fminf(fmaxf(v.w * s, -127.f), 127.f));
    ((char4*)g_a2)[i] = o;
}

// ---------------- launcher ----------------
extern "C" void kernel_launch(void* const* d_in, const int* in_sizes, int n_in,
                              void* d_out, int out_size) {
    const float* x     = (const float*)d_in[0];   // [8,2048,1024]
    const float* mask  = (const float*)d_in[1];   // [8,2048,1]
    const float* gamma = (const float*)d_in[2];   // [1024]
    const float* beta  = (const float*)d_in[3];   // [1024]
    const float* w1    = (const float*)d_in[4];   // [4096,1024]
    const float* b1    = (const float*)d_in[5];   // [4096]
    const float* w2    = (const float*)d_in[6];   // [1024,4096]
    const float* b2    = (const float*)d_in[7];   // [1024]
    float* out = (float*)d_out;

    const int wn4 = (FF * DIM) / 4;  // 1,048,576

    // weights: absmax -> quantize (idempotent across graph replays)
    absmax_k<0><<<2048, 256>>>((const float4*)w1, wn4);
    absmax_k<1><<<2048, 256>>>((const float4*)w2, wn4);
    quantw_k<0><<<wn4 / 256, 256>>>((const float4*)w1, wn4);
    quantw_k<1><<<wn4 / 256, 256>>>((const float4*)w2, wn4);

    // LN + act quant
    ln_quant_k<<<N_TOK, 256>>>((const float4*)x, (const float4*)gamma, (const float4*)beta);

    // GEMM1 + swish + row absmax
    gemm_s8_k<1><<<dim3(FF / 128, N_TOK / 128), 128>>>(b1, nullptr, nullptr, nullptr);

    // quantize h
    quant_h_k<<<(N_TOK * (FF / 4)) / 256, 256>>>();

    // GEMM2 + residual
    gemm_s8_k<2><<<dim3(DIM / 128, N_TOK / 128), 128>>>(b2, x, mask, out);
}